// round 9
// baseline (speedup 1.0000x reference)
#include <cuda_runtime.h>
#include <cuda_bf16.h>

// Two-kernel + PDL. LTS model (pinned R6+R8): scatter cost = REDG op count,
// width free -> keep ONE red.global.add.u64 per endpoint (fixed-point pack).
//   [63:56] z (zero-len slots) | [55:48] m (unit slots)
//   [47:24] Cfix = sum round((cos4t+1)*8192) | [23:0] Sfix likewise for sin4t
// Decode: C = Cfix/8192 - m, S = Sfix/8192 - m, deg = m + z.
// Per-node pair sum = (m^2 - C^2 - S^2)/16; P = sum deg(deg-1)/2.
// This round: (1) reduce uses atom.exch.b64 for read+clean in one op,
// (2) edge kernel 2 edges/thread (int2 index loads, 2x MLP),
// (3) cos4t/sin4t computed from unnormalized (dx,dy) with one rcp.

#define MAXN 65536

__device__ unsigned long long g_acc[MAXN];
__device__ double g_num;
__device__ double g_pairs;
__device__ unsigned g_done;

__device__ __forceinline__ void red_u64(unsigned long long* addr, unsigned long long v) {
    asm volatile("red.global.add.u64 [%0], %1;"
                 :: "l"(addr), "l"(v) : "memory");
}

__device__ __forceinline__ unsigned long long exch_u64(unsigned long long* addr) {
    unsigned long long old;
    asm volatile("atom.global.exch.b64 %0, [%1], 0;"
                 : "=l"(old) : "l"(addr) : "memory");
    return old;
}

__device__ __forceinline__ void do_edge(const float2* __restrict__ pos, int a, int b) {
    float2 pa = __ldg(pos + a);
    float2 pb = __ldg(pos + b);
    float x = pb.x - pa.x;
    float y = pb.y - pa.y;
    float x2 = x * x, y2 = y * y;
    float r2 = x2 + y2;

    unsigned long long payload;
    if (r2 > 0.f) {
        // cos4t = (x^4 - 6x^2y^2 + y^4)/r^4, sin4t = 4xy(x^2-y^2)/r^4
        float inv = __frcp_rn(r2 * r2);
        float d2 = x2 - y2;
        float xy = x * y;
        float c4 = (d2 * d2 - 4.f * xy * xy) * inv;
        float s4 = 4.f * xy * d2 * inv;
        unsigned cf = __float2uint_rn(fmaxf((c4 + 1.f) * 8192.f, 0.f));
        unsigned sf = __float2uint_rn(fmaxf((s4 + 1.f) * 8192.f, 0.f));
        payload = (1ULL << 48) | ((unsigned long long)cf << 24) | sf;
    } else {
        payload = 1ULL << 56;   // zero-length slot
    }
    red_u64(&g_acc[a], payload);
    red_u64(&g_acc[b], payload);
}

__global__ void edge_kernel(const float2* __restrict__ pos,
                            const int* __restrict__ src,
                            const int* __restrict__ dst,
                            int E) {
    int t = blockIdx.x * blockDim.x + threadIdx.x;
    int base = t * 2;
    if (base + 2 <= E) {
        int2 s = *(const int2*)(src + base);
        int2 d = *(const int2*)(dst + base);
        do_edge(pos, s.x, d.x);
        do_edge(pos, s.y, d.y);
    } else if (base < E) {
        do_edge(pos, src[base], dst[base]);
    }
#if __CUDA_ARCH__ >= 900
    cudaTriggerProgrammaticLaunchCompletion();
#endif
}

__global__ void reduce_finalize_kernel(float* __restrict__ out, int n) {
#if __CUDA_ARCH__ >= 900
    cudaGridDependencySynchronize();   // edge_kernel results now visible
#endif
    int i = blockIdx.x * blockDim.x + threadIdx.x;
    float num = 0.f, p = 0.f;
    if (i < n) {
        unsigned long long v = exch_u64(&g_acc[i]);   // read + self-clean, 1 op
        float S = (float)(v & 0xFFFFFFULL) * (1.f / 8192.f);
        float C = (float)((v >> 24) & 0xFFFFFFULL) * (1.f / 8192.f);
        float m = (float)((v >> 48) & 0xFFULL);
        float z = (float)(v >> 56);
        C -= m;                                 // remove +1 bias per unit slot
        S -= m;
        num = m * m - C * C - S * S;
        float deg = m + z;
        p = 0.5f * deg * (deg - 1.f);
    }

    // fp32 warp reduce
    #pragma unroll
    for (int off = 16; off > 0; off >>= 1) {
        num += __shfl_down_sync(0xffffffffu, num, off);
        p   += __shfl_down_sync(0xffffffffu, p, off);
    }

    __shared__ double sh_num[8];
    __shared__ double sh_p[8];
    int lane = threadIdx.x & 31;
    int wid  = threadIdx.x >> 5;
    if (lane == 0) { sh_num[wid] = (double)num; sh_p[wid] = (double)p; }
    __syncthreads();

    if (wid == 0) {
        double dnum = (lane < 8) ? sh_num[lane] : 0.0;
        double dp   = (lane < 8) ? sh_p[lane]   : 0.0;
        #pragma unroll
        for (int off = 4; off > 0; off >>= 1) {
            dnum += __shfl_down_sync(0xffffffffu, dnum, off);
            dp   += __shfl_down_sync(0xffffffffu, dp, off);
        }
        if (lane == 0) {
            atomicAdd(&g_num, dnum);
            atomicAdd(&g_pairs, dp);
            __threadfence();
            if (atomicAdd(&g_done, 1u) == gridDim.x - 1) {
                double total_num   = atomicAdd(&g_num, 0.0);
                double total_pairs = atomicAdd(&g_pairs, 0.0);
                double denom = 16.0 * total_pairs;
                out[0] = (denom > 0.0) ? (float)(total_num / denom) : 0.0f;
                g_num = 0.0;
                g_pairs = 0.0;
                g_done = 0u;
                __threadfence();
            }
        }
    }
}

extern "C" void kernel_launch(void* const* d_in, const int* in_sizes, int n_in,
                              void* d_out, int out_size) {
    const float* pos = (const float*)d_in[0];       // (1, N, 2)
    const int* edge_index = (const int*)d_in[2];    // (2, E)
    int N = in_sizes[0] / 2;
    int E = in_sizes[2] / 2;
    const int* src = edge_index;
    const int* dst = edge_index + E;
    float* out = (float*)d_out;

    const int tb = 256;
    int edge_threads = (E + 1) / 2;   // 2 edges per thread
    edge_kernel<<<(edge_threads + tb - 1) / tb, tb>>>((const float2*)pos, src, dst, E);

    // PDL: reduce kernel begins launching while edge_kernel drains;
    // it grid-dependency-syncs before reading edge results.
    cudaLaunchConfig_t cfg = {};
    cfg.gridDim  = dim3((N + tb - 1) / tb);
    cfg.blockDim = dim3(tb);
    cfg.dynamicSmemBytes = 0;
    cfg.stream = 0;
    cudaLaunchAttribute attr[1];
    attr[0].id = cudaLaunchAttributeProgrammaticStreamSerialization;
    attr[0].val.programmaticStreamSerializationAllowed = 1;
    cfg.attrs = attr;
    cfg.numAttrs = 1;
    cudaLaunchKernelEx(&cfg, reduce_finalize_kernel, out, N);
}

// round 10
// speedup vs baseline: 1.1194x; 1.1194x over previous
#include <cuda_runtime.h>
#include <cuda_bf16.h>

// R8 champion structure restored (16.86us), ONE change: reduce processes
// 2 nodes/thread via ulonglong2 (LDG.128 + STG.128), halving its op count.
//
// Scatter: ONE red.global.add.u64 per endpoint, fixed-point pack:
//   [63:56] z (zero-len slots) | [55:48] m (unit slots)
//   [47:24] Cfix = sum round((cos4t+1)*8192) | [23:0] Sfix for sin4t
// Decode: C = Cfix/8192 - m, S = Sfix/8192 - m, deg = m + z.
// Per-node pair sum = (m^2 - C^2 - S^2)/16; P = sum deg(deg-1)/2.
// loss = sum(...)/(16*P). State self-cleans (graph-replay safe).

#define MAXN 65536

__device__ __align__(16) unsigned long long g_acc[MAXN];
__device__ double g_num;
__device__ double g_pairs;
__device__ unsigned g_done;

__device__ __forceinline__ void red_u64(unsigned long long* addr, unsigned long long v) {
    asm volatile("red.global.add.u64 [%0], %1;"
                 :: "l"(addr), "l"(v) : "memory");
}

__global__ void edge_kernel(const float2* __restrict__ pos,
                            const int* __restrict__ src,
                            const int* __restrict__ dst,
                            int E) {
    int e = blockIdx.x * blockDim.x + threadIdx.x;
    if (e < E) {
        int a = src[e];
        int b = dst[e];
        float2 pa = __ldg(pos + a);
        float2 pb = __ldg(pos + b);
        float dx = pb.x - pa.x;
        float dy = pb.y - pa.y;
        float n2 = dx * dx + dy * dy;

        unsigned long long payload;
        if (n2 > 0.f) {
            float inv = rsqrtf(n2);
            float c = dx * inv, s = dy * inv;
            float c2 = c * c - s * s;
            float s2 = 2.f * c * s;
            float c4 = c2 * c2 - s2 * s2;
            float s4 = 2.f * c2 * s2;
            unsigned cf = __float2uint_rn(fmaxf((c4 + 1.f) * 8192.f, 0.f));
            unsigned sf = __float2uint_rn(fmaxf((s4 + 1.f) * 8192.f, 0.f));
            payload = (1ULL << 48) | ((unsigned long long)cf << 24) | sf;
        } else {
            payload = 1ULL << 56;   // zero-length slot: z += 1
        }
        red_u64(&g_acc[a], payload);
        red_u64(&g_acc[b], payload);
    }
#if __CUDA_ARCH__ >= 900
    cudaTriggerProgrammaticLaunchCompletion();
#endif
}

__device__ __forceinline__ float node_term(unsigned long long v, float& p_out) {
    float S = (float)(v & 0xFFFFFFULL) * (1.f / 8192.f);
    float C = (float)((v >> 24) & 0xFFFFFFULL) * (1.f / 8192.f);
    float m = (float)((v >> 48) & 0xFFULL);
    float z = (float)(v >> 56);
    C -= m;
    S -= m;
    float deg = m + z;
    p_out += 0.5f * deg * (deg - 1.f);
    return m * m - C * C - S * S;
}

__global__ void reduce_finalize_kernel(float* __restrict__ out, int n2) {
    // n2 = number of node PAIRS (each thread handles 2 nodes)
#if __CUDA_ARCH__ >= 900
    cudaGridDependencySynchronize();   // edge_kernel results now visible
#endif
    int i = blockIdx.x * blockDim.x + threadIdx.x;
    float num = 0.f, p = 0.f;
    if (i < n2) {
        ulonglong2 v = *reinterpret_cast<ulonglong2*>(&g_acc[i * 2]);
        *reinterpret_cast<ulonglong2*>(&g_acc[i * 2]) = make_ulonglong2(0ULL, 0ULL);
        num  = node_term(v.x, p);
        num += node_term(v.y, p);
    }

    // fp32 warp reduce
    #pragma unroll
    for (int off = 16; off > 0; off >>= 1) {
        num += __shfl_down_sync(0xffffffffu, num, off);
        p   += __shfl_down_sync(0xffffffffu, p, off);
    }

    __shared__ double sh_num[8];
    __shared__ double sh_p[8];
    int lane = threadIdx.x & 31;
    int wid  = threadIdx.x >> 5;
    if (lane == 0) { sh_num[wid] = (double)num; sh_p[wid] = (double)p; }
    __syncthreads();

    if (wid == 0) {
        double dnum = (lane < 8) ? sh_num[lane] : 0.0;
        double dp   = (lane < 8) ? sh_p[lane]   : 0.0;
        #pragma unroll
        for (int off = 4; off > 0; off >>= 1) {
            dnum += __shfl_down_sync(0xffffffffu, dnum, off);
            dp   += __shfl_down_sync(0xffffffffu, dp, off);
        }
        if (lane == 0) {
            atomicAdd(&g_num, dnum);
            atomicAdd(&g_pairs, dp);
            __threadfence();
            if (atomicAdd(&g_done, 1u) == gridDim.x - 1) {
                double total_num   = atomicAdd(&g_num, 0.0);
                double total_pairs = atomicAdd(&g_pairs, 0.0);
                double denom = 16.0 * total_pairs;
                out[0] = (denom > 0.0) ? (float)(total_num / denom) : 0.0f;
                g_num = 0.0;
                g_pairs = 0.0;
                g_done = 0u;
                __threadfence();
            }
        }
    }
}

extern "C" void kernel_launch(void* const* d_in, const int* in_sizes, int n_in,
                              void* d_out, int out_size) {
    const float* pos = (const float*)d_in[0];       // (1, N, 2)
    const int* edge_index = (const int*)d_in[2];    // (2, E)
    int N = in_sizes[0] / 2;
    int E = in_sizes[2] / 2;
    const int* src = edge_index;
    const int* dst = edge_index + E;
    float* out = (float*)d_out;

    const int tb = 256;
    edge_kernel<<<(E + tb - 1) / tb, tb>>>((const float2*)pos, src, dst, E);

    // PDL: reduce kernel begins launching while edge_kernel drains;
    // it grid-dependency-syncs before reading edge results.
    int n2 = (N + 1) / 2;   // node pairs (N=50000 even; MAXN padding is zero)
    cudaLaunchConfig_t cfg = {};
    cfg.gridDim  = dim3((n2 + tb - 1) / tb);
    cfg.blockDim = dim3(tb);
    cfg.dynamicSmemBytes = 0;
    cfg.stream = 0;
    cudaLaunchAttribute attr[1];
    attr[0].id = cudaLaunchAttributeProgrammaticStreamSerialization;
    attr[0].val.programmaticStreamSerializationAllowed = 1;
    cfg.attrs = attr;
    cfg.numAttrs = 1;
    cudaLaunchKernelEx(&cfg, reduce_finalize_kernel, out, n2);
}